// round 16
// baseline (speedup 1.0000x reference)
#include <cuda_runtime.h>
#include <cuda_fp16.h>
#include <math.h>
#include <stdint.h>

#define Bb 16
#define Hh 64
#define Ww 64
#define Cc 256
#define NPIX (Bb*Hh*Ww)   // 65536

// ---------------- scratch (static device allocations) ----------------
__device__ __half g_Ph[(size_t)NPIX * 768];    // perceived  fp16  [pix][j*256+c]
__device__ __half g_HIDh[(size_t)NPIX * 512];  // hidden     fp16
__device__ __half g_HNEWh[(size_t)NPIX * 256]; // h_new      fp16 (single copy)
__device__ __half g_QKVh[(size_t)NPIX * 768];  // qkv        fp16
__device__ __half g_W1h[512 * 768];            // permuted to match P layout
__device__ __half g_W2h[256 * 512];
__device__ __half g_WQh[768 * 256];

// ============================ helpers =============================
__device__ __forceinline__ uint32_t smem_u32(const void* p) {
    uint32_t a;
    asm("{ .reg .u64 t; cvta.to.shared.u64 t, %1; cvt.u32.u64 %0, t; }"
        : "=r"(a) : "l"(p));
    return a;
}

#define CP_ASYNC16(sa, ga) \
    asm volatile("cp.async.cg.shared.global [%0], [%1], 16;" :: "r"(sa), "l"(ga) : "memory")
#define CP_COMMIT() asm volatile("cp.async.commit_group;" ::: "memory")

// PDL: trigger dependent-grid launch / wait for upstream grid memory
#define PDL_TRIGGER() asm volatile("griddepcontrol.launch_dependents;" ::: "memory")
#define PDL_WAIT()    asm volatile("griddepcontrol.wait;" ::: "memory")
#define PREFETCH_L2(p) asm volatile("prefetch.global.L2 [%0];" :: "l"(p))

__device__ __forceinline__ void ldmatrix_x4(uint32_t& r0, uint32_t& r1,
                                            uint32_t& r2, uint32_t& r3, uint32_t addr) {
    asm volatile("ldmatrix.sync.aligned.m8n8.x4.shared.b16 {%0,%1,%2,%3}, [%4];"
                 : "=r"(r0), "=r"(r1), "=r"(r2), "=r"(r3) : "r"(addr));
}

__device__ __forceinline__ void mma_f16(float& c0, float& c1, float& c2, float& c3,
                                        uint32_t a0, uint32_t a1, uint32_t a2, uint32_t a3,
                                        uint32_t b0, uint32_t b1) {
    asm volatile(
        "mma.sync.aligned.m16n8k16.row.col.f32.f16.f16.f32 "
        "{%0,%1,%2,%3},{%4,%5,%6,%7},{%8,%9},{%0,%1,%2,%3};"
        : "+f"(c0), "+f"(c1), "+f"(c2), "+f"(c3)
        : "r"(a0), "r"(a1), "r"(a2), "r"(a3), "r"(b0), "r"(b1));
}

__device__ __forceinline__ float gelu_exact(float v) {
    return 0.5f * v * (1.0f + erff(v * 0.70710678118654752f));
}

__device__ __forceinline__ float2 u2f2(uint32_t u) {
    __half2 h = *reinterpret_cast<__half2*>(&u);
    return __half22float2(h);
}

// ==== fused: depthwise conv (blocks < NCONVBLK) + weight cvt (rest) ====
#define XSEG 16
#define NCONVBLK (Bb*Hh*4)           // 4096
#define N_W1 (512*768)
#define N_W2 (256*512)
#define N_WQ (768*256)
#define NCVT (N_W1 + N_W2 + N_WQ)    // 720896
#define NCVTBLK ((NCVT + 255) / 256) // 2816

__global__ void __launch_bounds__(256)
dwconv_cvt_kernel(const float* __restrict__ h,
                  const float* __restrict__ wp,   // (3C,1,3,3)
                  const float* __restrict__ bp,   // (3C,)
                  __half* __restrict__ P,         // [pix][j*256+c]
                  const float* __restrict__ w1,
                  const float* __restrict__ w2,
                  const float* __restrict__ wq,
                  __half* __restrict__ d1,
                  __half* __restrict__ d2,
                  __half* __restrict__ dq)
{
    int blk = blockIdx.x;
    if (blk >= NCONVBLK) {
        int i = (blk - NCONVBLK) * 256 + threadIdx.x;
        if (i < N_W1) {
            int row = i / 768, p = i % 768;
            int j = p >> 8, c = p & 255;
            d1[i] = __float2half(w1[row * 768 + 3 * c + j]);
        } else if (i < N_W1 + N_W2) {
            int k = i - N_W1;
            d2[k] = __float2half(w2[k]);
        } else if (i < NCVT) {
            int k = i - N_W1 - N_W2;
            dq[k] = __float2half(wq[k]);
        }
        return;
    }

    int x0  = (blk & 3) * XSEG;
    int by  = blk >> 2;
    int y   = by & (Hh - 1);
    int b   = by >> 6;
    int c   = threadIdx.x;

    float w[3][9];
    #pragma unroll
    for (int j = 0; j < 3; j++)
        #pragma unroll
        for (int t = 0; t < 9; t++)
            w[j][t] = wp[(3*c + j)*9 + t];
    float b0 = bp[3*c+0], b1 = bp[3*c+1], b2 = bp[3*c+2];

    const float* base = h + (size_t)(b*Hh*Ww)*Cc + c;
    bool hm = (y > 0), hp = (y < Hh - 1);
    size_t rm = (size_t)(y - 1) * Ww * Cc;
    size_t rc = (size_t)(y    ) * Ww * Cc;
    size_t rp = (size_t)(y + 1) * Ww * Cc;

    auto load_col = [&](float* v, int cx) {
        if (cx >= 0 && cx < Ww) {
            size_t xo = (size_t)cx * Cc;
            v[0] = hm ? base[rm + xo] : 0.f;
            v[1] =      base[rc + xo];
            v[2] = hp ? base[rp + xo] : 0.f;
        } else {
            v[0] = v[1] = v[2] = 0.f;
        }
    };

    float p0[3], p1[3], p2[3], p3[3], p4[3];
    load_col(p0, x0 - 1);
    load_col(p1, x0);
    load_col(p2, x0 + 1);

    __half* Pb = P + (size_t)(b*Hh + y) * Ww * 768 + c;

    for (int x = x0; x < x0 + XSEG; x += 2) {
        load_col(p3, x + 2);
        load_col(p4, x + 3);

        float a0 = b0, a1 = b1, a2 = b2;
        float d0 = b0, d1v = b1, d2v = b2;
        #pragma unroll
        for (int r = 0; r < 3; r++) {
            a0 = fmaf(p0[r], w[0][r*3+0], a0);
            a0 = fmaf(p1[r], w[0][r*3+1], a0);
            a0 = fmaf(p2[r], w[0][r*3+2], a0);
            a1 = fmaf(p0[r], w[1][r*3+0], a1);
            a1 = fmaf(p1[r], w[1][r*3+1], a1);
            a1 = fmaf(p2[r], w[1][r*3+2], a1);
            a2 = fmaf(p0[r], w[2][r*3+0], a2);
            a2 = fmaf(p1[r], w[2][r*3+1], a2);
            a2 = fmaf(p2[r], w[2][r*3+2], a2);

            d0  = fmaf(p1[r], w[0][r*3+0], d0);
            d0  = fmaf(p2[r], w[0][r*3+1], d0);
            d0  = fmaf(p3[r], w[0][r*3+2], d0);
            d1v = fmaf(p1[r], w[1][r*3+0], d1v);
            d1v = fmaf(p2[r], w[1][r*3+1], d1v);
            d1v = fmaf(p3[r], w[1][r*3+2], d1v);
            d2v = fmaf(p1[r], w[2][r*3+0], d2v);
            d2v = fmaf(p2[r], w[2][r*3+1], d2v);
            d2v = fmaf(p3[r], w[2][r*3+2], d2v);
        }

        size_t o = (size_t)x * 768;
        Pb[o       ] = __float2half(a0);
        Pb[o +  256] = __float2half(a1);
        Pb[o +  512] = __float2half(a2);
        Pb[o +  768] = __float2half(d0);
        Pb[o + 1024] = __float2half(d1v);
        Pb[o + 1280] = __float2half(d2v);

        #pragma unroll
        for (int r = 0; r < 3; r++) {
            p0[r] = p2[r];
            p1[r] = p3[r];
            p2[r] = p4[r];
        }
    }
}

// =========== fp16 tensor-core GEMM: C[M,N] = A[M,K] @ B[N,K]^T ===============
// Block 128x128, warp tile 64x32, 2 CTAs/SM. Register double-buffered frags.
// PDL: if B is finalized >=2 kernels upstream (EPI!=1), L2-prefetch it before
// griddepcontrol.wait; trigger dependents after the mainloop (before epilogue).
// EPI: 1 = gelu(+bias) -> fp16 Ch ; 2 = +bias+add -> fp16 Ch ONLY ;
//      3 = +bias -> fp16 Ch only
#define BK 64
#define RSTR 72
#define OPB (128 * RSTR * 2)
#define STG (2 * OPB)
#define NSTAGE 3

template<int EPI>
__global__ void __launch_bounds__(256, 2)
hgemm_kernel(const __half* __restrict__ A, const __half* __restrict__ Bw,
             const float* __restrict__ bias, const float* __restrict__ add,
             __half* __restrict__ Ch,
             int M, int N, int K, int nbn)
{
    extern __shared__ char dsm_raw[];
    uint32_t dbase = smem_u32(dsm_raw);

    int tid  = threadIdx.x;
    int lane = tid & 31;
    int wid  = tid >> 5;
    int wm   = wid >> 2;
    int wn   = wid & 3;

    int bid = blockIdx.x;
    int bm = bid / nbn;
    int bn = bid - bm * nbn;

    const __half* Ag = A  + (size_t)bm * 128 * K;
    const __half* Bg = Bw + (size_t)bn * 128 * K;

    // --- pre-wait: prefetch weight tile into L2 (safe when EPI != 1:
    // weights were written by dwconv_cvt, >=2 kernels upstream, and the
    // transitive griddepcontrol chain guarantees that grid completed) ---
    if (EPI != 1) {
        int btile = 128 * K * 2;
        const char* bp0 = (const char*)Bg;
        for (int off = tid * 128; off < btile; off += 256 * 128)
            PREFETCH_L2(bp0 + off);
    }
    PDL_WAIT();

    auto load_stage = [&](int kt, int buf) {
        uint32_t sA = dbase + (uint32_t)buf * STG;
        uint32_t sB = sA + OPB;
        int kofs = kt * BK;
        #pragma unroll
        for (int i = 0; i < 4; i++) {
            int ci  = tid + 256 * i;
            int row = ci >> 3;
            int kc  = (ci & 7) * 8;
            const __half* ga = Ag + (size_t)row * K + kofs + kc;
            const __half* gb = Bg + (size_t)row * K + kofs + kc;
            uint32_t so = (uint32_t)(row * (RSTR * 2) + kc * 2);
            CP_ASYNC16(sA + so, ga);
            CP_ASYNC16(sB + so, gb);
        }
        CP_COMMIT();
    };

    float acc[4][4][4];
    #pragma unroll
    for (int i = 0; i < 4; i++)
        #pragma unroll
        for (int j = 0; j < 4; j++)
            #pragma unroll
            for (int r = 0; r < 4; r++) acc[i][j][r] = 0.f;

    int a_m  = (lane & 7) + ((lane >> 3) & 1) * 8;
    int a_kh = ((lane >> 4) & 1) * 8;
    int b_n  = (lane & 7) + ((lane >> 4) & 1) * 8;
    int b_kh = ((lane >> 3) & 1) * 8;

    uint32_t af[2][4][4];
    uint32_t bf[2][4][2];

    int NT = K / BK;
    load_stage(0, 0);
    load_stage(1, 1);

    for (int kt = 0; kt < NT; kt++) {
        if (kt + 2 < NT) {
            asm volatile("cp.async.wait_group 1;" ::: "memory");
        } else {
            asm volatile("cp.async.wait_group 0;" ::: "memory");
        }
        __syncthreads();
        if (kt + 2 < NT) load_stage(kt + 2, (kt + 2) % NSTAGE);

        uint32_t sA = dbase + (uint32_t)(kt % NSTAGE) * STG;
        uint32_t sB = sA + OPB;

        #pragma unroll
        for (int i = 0; i < 4; i++) {
            int m = wm * 64 + i * 16 + a_m;
            ldmatrix_x4(af[0][i][0], af[0][i][1], af[0][i][2], af[0][i][3],
                        sA + (uint32_t)((m * RSTR + a_kh) * 2));
        }
        #pragma unroll
        for (int j = 0; j < 2; j++) {
            int n = wn * 32 + j * 16 + b_n;
            ldmatrix_x4(bf[0][2*j][0], bf[0][2*j][1], bf[0][2*j+1][0], bf[0][2*j+1][1],
                        sB + (uint32_t)((n * RSTR + b_kh) * 2));
        }

        #pragma unroll
        for (int s = 0; s < 4; s++) {
            int cur = s & 1;
            if (s < 3) {
                int nxt = (s + 1) & 1;
                int k0 = (s + 1) * 16;
                #pragma unroll
                for (int i = 0; i < 4; i++) {
                    int m = wm * 64 + i * 16 + a_m;
                    ldmatrix_x4(af[nxt][i][0], af[nxt][i][1], af[nxt][i][2], af[nxt][i][3],
                                sA + (uint32_t)((m * RSTR + k0 + a_kh) * 2));
                }
                #pragma unroll
                for (int j = 0; j < 2; j++) {
                    int n = wn * 32 + j * 16 + b_n;
                    ldmatrix_x4(bf[nxt][2*j][0], bf[nxt][2*j][1],
                                bf[nxt][2*j+1][0], bf[nxt][2*j+1][1],
                                sB + (uint32_t)((n * RSTR + k0 + b_kh) * 2));
                }
            }
            #pragma unroll
            for (int i = 0; i < 4; i++)
                #pragma unroll
                for (int j = 0; j < 4; j++)
                    mma_f16(acc[i][j][0], acc[i][j][1], acc[i][j][2], acc[i][j][3],
                            af[cur][i][0], af[cur][i][1], af[cur][i][2], af[cur][i][3],
                            bf[cur][j][0], bf[cur][j][1]);
        }
    }

    // mainloop done: allow the dependent grid to start scheduling now;
    // its griddepcontrol.wait still covers the epilogue writes below.
    PDL_TRIGGER();

    int gid = lane >> 2;
    int tig = lane & 3;

    #pragma unroll
    for (int i = 0; i < 4; i++) {
        #pragma unroll
        for (int j = 0; j < 4; j++) {
            int rrow = bm*128 + wm*64 + i*16 + gid;
            int ncol = bn*128 + wn*32 + j*8 + tig*2;
            float b0v = bias[ncol], b1v = bias[ncol+1];

            float v0 = acc[i][j][0] + b0v;
            float v1 = acc[i][j][1] + b1v;
            float v2 = acc[i][j][2] + b0v;
            float v3 = acc[i][j][3] + b1v;
            if (EPI == 1) {
                v0 = gelu_exact(v0); v1 = gelu_exact(v1);
                v2 = gelu_exact(v2); v3 = gelu_exact(v3);
            }
            size_t o0 = (size_t)rrow * N + ncol;
            size_t o1 = (size_t)(rrow + 8) * N + ncol;
            if (EPI == 2) {
                float2 r0a = *(const float2*)(add + o0);
                float2 r1a = *(const float2*)(add + o1);
                v0 += r0a.x; v1 += r0a.y; v2 += r1a.x; v3 += r1a.y;
            }
            *(__half2*)(Ch + o0) = __floats2half2_rn(v0, v1);
            *(__half2*)(Ch + o1) = __floats2half2_rn(v2, v3);
        }
    }
}

// ==== 3x3 local attention: warp per PIXEL-PAIR, 16B loads, WRITE-ONLY out ===
// PDL: hnew is finalized >=2 kernels upstream -> load it BEFORE the wait;
// qkv (direct predecessor) only after griddepcontrol.wait.
__global__ void attn_kernel(const __half* __restrict__ qkv,
                            const __half* __restrict__ hnew,
                            float* __restrict__ out)
{
    int gtid = blockIdx.x * blockDim.x + threadIdx.x;
    int pair = gtid >> 5;
    int lane = gtid & 31;
    if (pair >= NPIX / 2) { PDL_WAIT(); return; }

    int pix0 = pair * 2;
    int x0 = pix0 & (Ww - 1);            // even
    int y  = (pix0 >> 6) & (Hh - 1);
    int b  = pix0 >> 12;

    int ch = lane * 8;                   // first owned channel

    // pre-wait: hnew loads (safe — produced 2 kernels upstream)
    uint4 hu0 = *(const uint4*)(hnew + (size_t)pix0 * 256 + ch);
    uint4 hu1 = *(const uint4*)(hnew + (size_t)(pix0 + 1) * 256 + ch);

    PDL_WAIT();

    uint4 q0u = *(const uint4*)(qkv + (size_t)pix0 * 768 + ch);
    uint4 q1u = *(const uint4*)(qkv + (size_t)(pix0 + 1) * 768 + ch);
    float2 q0[4], q1[4];
    q0[0] = u2f2(q0u.x); q0[1] = u2f2(q0u.y); q0[2] = u2f2(q0u.z); q0[3] = u2f2(q0u.w);
    q1[0] = u2f2(q1u.x); q1[1] = u2f2(q1u.y); q1[2] = u2f2(q1u.z); q1[3] = u2f2(q1u.w);

    const float scale = 0.0625f;   // 1/sqrt(256)
    float s0[9], s1[9];

    #pragma unroll
    for (int r = 0; r < 3; r++) {
        int ny = y + r - 1;
        bool rowok = (ny >= 0 && ny < Hh);
        #pragma unroll
        for (int c = 0; c < 4; c++) {
            int cx = x0 - 1 + c;
            bool ok = rowok && (cx >= 0 && cx < Ww);
            float p0 = 0.f, p1 = 0.f;
            if (ok) {
                uint4 ku = *(const uint4*)(qkv +
                    (size_t)((b*Hh + ny)*Ww + cx) * 768 + 256 + ch);
                float2 kf[4];
                kf[0] = u2f2(ku.x); kf[1] = u2f2(ku.y);
                kf[2] = u2f2(ku.z); kf[3] = u2f2(ku.w);
                #pragma unroll
                for (int rr = 0; rr < 4; rr++) {
                    if (c < 3) {
                        p0 = fmaf(q0[rr].x, kf[rr].x, p0);
                        p0 = fmaf(q0[rr].y, kf[rr].y, p0);
                    }
                    if (c > 0) {
                        p1 = fmaf(q1[rr].x, kf[rr].x, p1);
                        p1 = fmaf(q1[rr].y, kf[rr].y, p1);
                    }
                }
            }
            if (c < 3) {
                #pragma unroll
                for (int o = 16; o > 0; o >>= 1) p0 += __shfl_xor_sync(0xffffffff, p0, o);
                s0[r*3 + c] = ok ? p0 * scale : 0.f;
            }
            if (c > 0) {
                #pragma unroll
                for (int o = 16; o > 0; o >>= 1) p1 += __shfl_xor_sync(0xffffffff, p1, o);
                s1[r*3 + c - 1] = ok ? p1 * scale : 0.f;
            }
        }
    }

    float m0 = s0[0], m1 = s1[0];
    #pragma unroll
    for (int i = 1; i < 9; i++) { m0 = fmaxf(m0, s0[i]); m1 = fmaxf(m1, s1[i]); }
    float e0[9], e1[9], sum0 = 0.f, sum1 = 0.f;
    #pragma unroll
    for (int i = 0; i < 9; i++) {
        e0[i] = expf(s0[i] - m0); sum0 += e0[i];
        e1[i] = expf(s1[i] - m1); sum1 += e1[i];
    }
    float inv0 = 1.f / sum0, inv1 = 1.f / sum1;

    float2 a0[4], a1[4];
    #pragma unroll
    for (int r = 0; r < 4; r++) { a0[r] = make_float2(0.f,0.f); a1[r] = make_float2(0.f,0.f); }

    #pragma unroll
    for (int r = 0; r < 3; r++) {
        int ny = y + r - 1;
        bool rowok = (ny >= 0 && ny < Hh);
        #pragma unroll
        for (int c = 0; c < 4; c++) {
            int cx = x0 - 1 + c;
            bool ok = rowok && (cx >= 0 && cx < Ww);
            if (!ok) continue;
            float w0 = (c < 3) ? e0[r*3 + c] * inv0 : 0.f;
            float w1 = (c > 0) ? e1[r*3 + c - 1] * inv1 : 0.f;
            uint4 vu = *(const uint4*)(qkv +
                (size_t)((b*Hh + ny)*Ww + cx) * 768 + 512 + ch);
            float2 vf[4];
            vf[0] = u2f2(vu.x); vf[1] = u2f2(vu.y);
            vf[2] = u2f2(vu.z); vf[3] = u2f2(vu.w);
            #pragma unroll
            for (int rr = 0; rr < 4; rr++) {
                if (c < 3) {
                    a0[rr].x = fmaf(w0, vf[rr].x, a0[rr].x);
                    a0[rr].y = fmaf(w0, vf[rr].y, a0[rr].y);
                }
                if (c > 0) {
                    a1[rr].x = fmaf(w1, vf[rr].x, a1[rr].x);
                    a1[rr].y = fmaf(w1, vf[rr].y, a1[rr].y);
                }
            }
        }
    }

    // out = float(hnew fp16) + attn   (pure store, no RMW)
    {
        float2 hf[4];
        hf[0] = u2f2(hu0.x); hf[1] = u2f2(hu0.y); hf[2] = u2f2(hu0.z); hf[3] = u2f2(hu0.w);
        float* ob = out + (size_t)pix0 * 256 + ch;
        *(float4*)(ob)     = make_float4(hf[0].x + a0[0].x, hf[0].y + a0[0].y,
                                         hf[1].x + a0[1].x, hf[1].y + a0[1].y);
        *(float4*)(ob + 4) = make_float4(hf[2].x + a0[2].x, hf[2].y + a0[2].y,
                                         hf[3].x + a0[3].x, hf[3].y + a0[3].y);
    }
    {
        float2 hf[4];
        hf[0] = u2f2(hu1.x); hf[1] = u2f2(hu1.y); hf[2] = u2f2(hu1.z); hf[3] = u2f2(hu1.w);
        float* ob = out + (size_t)(pix0 + 1) * 256 + ch;
        *(float4*)(ob)     = make_float4(hf[0].x + a1[0].x, hf[0].y + a1[0].y,
                                         hf[1].x + a1[1].x, hf[1].y + a1[1].y);
        *(float4*)(ob + 4) = make_float4(hf[2].x + a1[2].x, hf[2].y + a1[2].y,
                                         hf[3].x + a1[3].x, hf[3].y + a1[3].y);
    }
}

// ---------------- launch ------------------------------------------------------
extern "C" void kernel_launch(void* const* d_in, const int* in_sizes, int n_in,
                              void* d_out, int out_size)
{
    const float* h      = (const float*)d_in[0];
    const float* w_perc = (const float*)d_in[1];
    const float* b_perc = (const float*)d_in[2];
    const float* w_up1  = (const float*)d_in[3];
    const float* b_up1  = (const float*)d_in[4];
    const float* w_up2  = (const float*)d_in[5];
    const float* b_up2  = (const float*)d_in[6];
    const float* w_qkv  = (const float*)d_in[7];
    const float* b_qkv  = (const float*)d_in[8];
    float* out = (float*)d_out;

    __half *Ph, *HIDh, *HNEWh, *QKVh, *W1h, *W2h, *WQh;
    cudaGetSymbolAddress((void**)&Ph,    g_Ph);
    cudaGetSymbolAddress((void**)&HIDh,  g_HIDh);
    cudaGetSymbolAddress((void**)&HNEWh, g_HNEWh);
    cudaGetSymbolAddress((void**)&QKVh,  g_QKVh);
    cudaGetSymbolAddress((void**)&W1h,   g_W1h);
    cudaGetSymbolAddress((void**)&W2h,   g_W2h);
    cudaGetSymbolAddress((void**)&WQh,   g_WQh);

    size_t dsm = (size_t)NSTAGE * STG;   // 110592
    cudaFuncSetAttribute(hgemm_kernel<1>, cudaFuncAttributeMaxDynamicSharedMemorySize, (int)dsm);
    cudaFuncSetAttribute(hgemm_kernel<2>, cudaFuncAttributeMaxDynamicSharedMemorySize, (int)dsm);
    cudaFuncSetAttribute(hgemm_kernel<3>, cudaFuncAttributeMaxDynamicSharedMemorySize, (int)dsm);

    cudaLaunchAttribute pdl[1];
    pdl[0].id = cudaLaunchAttributeProgrammaticStreamSerialization;
    pdl[0].val.programmaticStreamSerializationAllowed = 1;

    // 1) fused: dwconv (P) + weight conversion, one launch (normal launch)
    dwconv_cvt_kernel<<<NCONVBLK + NCVTBLK, 256>>>(h, w_perc, b_perc, Ph,
                                                   w_up1, w_up2, w_qkv,
                                                   W1h, W2h, WQh);

    // 2) HIDh = gelu(Ph @ W1h^T + b_up1)  fp16 [NPIX, 512]   (PDL consumer)
    {
        int nbm = NPIX / 128, nbn = 512 / 128;
        cudaLaunchConfig_t cfg = {};
        cfg.gridDim = dim3(nbm * nbn); cfg.blockDim = dim3(256);
        cfg.dynamicSmemBytes = dsm; cfg.stream = 0;
        cfg.attrs = pdl; cfg.numAttrs = 1;
        cudaLaunchKernelEx(&cfg, hgemm_kernel<1>,
                           (const __half*)Ph, (const __half*)W1h, b_up1,
                           (const float*)nullptr, HIDh, (int)NPIX, 512, 768, nbn);
    }
    // 3) h_new = HIDh @ W2h^T + b_up2 + h  -> HNEWh fp16 ONLY
    {
        int nbm = NPIX / 128, nbn = 256 / 128;
        cudaLaunchConfig_t cfg = {};
        cfg.gridDim = dim3(nbm * nbn); cfg.blockDim = dim3(256);
        cfg.dynamicSmemBytes = dsm; cfg.stream = 0;
        cfg.attrs = pdl; cfg.numAttrs = 1;
        cudaLaunchKernelEx(&cfg, hgemm_kernel<2>,
                           (const __half*)HIDh, (const __half*)W2h, b_up2,
                           h, HNEWh, (int)NPIX, 256, 512, nbn);
    }
    // 4) QKVh = HNEWh @ WQh^T + b_qkv  fp16 [NPIX, 768]
    {
        int nbm = NPIX / 128, nbn = 768 / 128;
        cudaLaunchConfig_t cfg = {};
        cfg.gridDim = dim3(nbm * nbn); cfg.blockDim = dim3(256);
        cfg.dynamicSmemBytes = dsm; cfg.stream = 0;
        cfg.attrs = pdl; cfg.numAttrs = 1;
        cudaLaunchKernelEx(&cfg, hgemm_kernel<3>,
                           (const __half*)HNEWh, (const __half*)WQh, b_qkv,
                           (const float*)nullptr, QKVh, (int)NPIX, 768, 256, nbn);
    }
    // 5) out = float(HNEWh) + local_attn(QKVh)   (PDL consumer)
    {
        int threads = 256;
        int blocks = (NPIX / 2 * 32) / threads;   // 4096
        cudaLaunchConfig_t cfg = {};
        cfg.gridDim = dim3(blocks); cfg.blockDim = dim3(threads);
        cfg.dynamicSmemBytes = 0; cfg.stream = 0;
        cfg.attrs = pdl; cfg.numAttrs = 1;
        cudaLaunchKernelEx(&cfg, attn_kernel,
                           (const __half*)QKVh, (const __half*)HNEWh, out);
    }
}

// round 17
// speedup vs baseline: 1.0528x; 1.0528x over previous
#include <cuda_runtime.h>
#include <cuda_fp16.h>
#include <math.h>
#include <stdint.h>

#define Bb 16
#define Hh 64
#define Ww 64
#define Cc 256
#define NPIX (Bb*Hh*Ww)   // 65536

// ---------------- scratch (static device allocations) ----------------
__device__ __half g_Ph[(size_t)NPIX * 768];    // perceived  fp16  [pix][j*256+c]
__device__ __half g_HIDh[(size_t)NPIX * 512];  // hidden     fp16
__device__ __half g_HNEWh[(size_t)NPIX * 256]; // h_new      fp16 (single copy)
__device__ __half g_QKVh[(size_t)NPIX * 768];  // qkv        fp16
__device__ __half g_W1h[512 * 768];            // permuted to match P layout
__device__ __half g_W2h[256 * 512];
__device__ __half g_WQh[768 * 256];

// ============================ helpers =============================
__device__ __forceinline__ uint32_t smem_u32(const void* p) {
    uint32_t a;
    asm("{ .reg .u64 t; cvta.to.shared.u64 t, %1; cvt.u32.u64 %0, t; }"
        : "=r"(a) : "l"(p));
    return a;
}

#define CP_ASYNC16(sa, ga) \
    asm volatile("cp.async.cg.shared.global [%0], [%1], 16;" :: "r"(sa), "l"(ga) : "memory")
#define CP_COMMIT() asm volatile("cp.async.commit_group;" ::: "memory")

__device__ __forceinline__ void ldmatrix_x4(uint32_t& r0, uint32_t& r1,
                                            uint32_t& r2, uint32_t& r3, uint32_t addr) {
    asm volatile("ldmatrix.sync.aligned.m8n8.x4.shared.b16 {%0,%1,%2,%3}, [%4];"
                 : "=r"(r0), "=r"(r1), "=r"(r2), "=r"(r3) : "r"(addr));
}

__device__ __forceinline__ void mma_f16(float& c0, float& c1, float& c2, float& c3,
                                        uint32_t a0, uint32_t a1, uint32_t a2, uint32_t a3,
                                        uint32_t b0, uint32_t b1) {
    asm volatile(
        "mma.sync.aligned.m16n8k16.row.col.f32.f16.f16.f32 "
        "{%0,%1,%2,%3},{%4,%5,%6,%7},{%8,%9},{%0,%1,%2,%3};"
        : "+f"(c0), "+f"(c1), "+f"(c2), "+f"(c3)
        : "r"(a0), "r"(a1), "r"(a2), "r"(a3), "r"(b0), "r"(b1));
}

__device__ __forceinline__ float gelu_exact(float v) {
    return 0.5f * v * (1.0f + erff(v * 0.70710678118654752f));
}

__device__ __forceinline__ float2 u2f2(uint32_t u) {
    __half2 h = *reinterpret_cast<__half2*>(&u);
    return __half22float2(h);
}

// ==== fused: depthwise conv (2 output rows/block) + weight cvt (rest) ====
#define XSEG 16
#define NCONVBLK (Bb*(Hh/2)*4)       // 2048
#define N_W1 (512*768)
#define N_W2 (256*512)
#define N_WQ (768*256)
#define NCVT (N_W1 + N_W2 + N_WQ)    // 720896
#define NCVTBLK ((NCVT + 255) / 256) // 2816

__global__ void __launch_bounds__(256)
dwconv_cvt_kernel(const float* __restrict__ h,
                  const float* __restrict__ wp,   // (3C,1,3,3)
                  const float* __restrict__ bp,   // (3C,)
                  __half* __restrict__ P,         // [pix][j*256+c]
                  const float* __restrict__ w1,
                  const float* __restrict__ w2,
                  const float* __restrict__ wq,
                  __half* __restrict__ d1,
                  __half* __restrict__ d2,
                  __half* __restrict__ dq)
{
    int blk = blockIdx.x;
    if (blk >= NCONVBLK) {
        int i = (blk - NCONVBLK) * 256 + threadIdx.x;
        if (i < N_W1) {
            int row = i / 768, p = i % 768;
            int j = p >> 8, c = p & 255;
            d1[i] = __float2half(w1[row * 768 + 3 * c + j]);
        } else if (i < N_W1 + N_W2) {
            int k = i - N_W1;
            d2[k] = __float2half(w2[k]);
        } else if (i < NCVT) {
            int k = i - N_W1 - N_W2;
            dq[k] = __float2half(wq[k]);
        }
        return;
    }

    // ---- depthwise conv: 2 output rows (y0, y0+1), XSEG pixels each ----
    int x0 = (blk & 3) * XSEG;
    int t  = blk >> 2;                // 0..Bb*Hh/2-1
    int ry = t & (Hh/2 - 1);
    int b  = t >> 5;                  // Hh/2 = 32
    int y0 = ry * 2;
    int c  = threadIdx.x;

    float w[3][9];
    #pragma unroll
    for (int j = 0; j < 3; j++)
        #pragma unroll
        for (int tt = 0; tt < 9; tt++)
            w[j][tt] = wp[(3*c + j)*9 + tt];
    float b0 = bp[3*c+0], b1 = bp[3*c+1], b2 = bp[3*c+2];

    const float* base = h + (size_t)(b*Hh*Ww)*Cc + c;
    bool vm = (y0 > 0);
    bool v2 = (y0 + 2 < Hh);
    size_t rA = (size_t)(y0 - 1) * Ww * Cc;   // row y0-1
    size_t rB = (size_t)(y0    ) * Ww * Cc;   // row y0
    size_t rC = (size_t)(y0 + 1) * Ww * Cc;   // row y0+1
    size_t rD = (size_t)(y0 + 2) * Ww * Cc;   // row y0+2

    // 4-tall column window: v[0]=y0-1, v[1]=y0, v[2]=y0+1, v[3]=y0+2
    auto load_col = [&](float* v, int cx) {
        if (cx >= 0 && cx < Ww) {
            size_t xo = (size_t)cx * Cc;
            v[0] = vm ? base[rA + xo] : 0.f;
            v[1] =      base[rB + xo];
            v[2] =      base[rC + xo];
            v[3] = v2 ? base[rD + xo] : 0.f;
        } else {
            v[0] = v[1] = v[2] = v[3] = 0.f;
        }
    };

    float p0[4], p1[4], p2[4], p3[4], p4[4];
    load_col(p0, x0 - 1);
    load_col(p1, x0);
    load_col(p2, x0 + 1);

    __half* Pb0 = P + (size_t)(b*Hh + y0) * Ww * 768 + c;
    __half* Pb1 = Pb0 + (size_t)Ww * 768;

    for (int x = x0; x < x0 + XSEG; x += 2) {
        load_col(p3, x + 2);
        load_col(p4, x + 3);

        // row y0, pixel x:   window rows 0..2 ; row y0+1: rows 1..3
        float a0 = b0, a1 = b1, a2 = b2;       // (y0,   x)
        float d0 = b0, d1v = b1, d2v = b2;     // (y0,   x+1)
        float e0 = b0, e1 = b1, e2 = b2;       // (y0+1, x)
        float f0 = b0, f1 = b1, f2 = b2;       // (y0+1, x+1)
        #pragma unroll
        for (int r = 0; r < 3; r++) {
            // output row y0 (uses window rows r)
            a0 = fmaf(p0[r], w[0][r*3+0], a0);
            a0 = fmaf(p1[r], w[0][r*3+1], a0);
            a0 = fmaf(p2[r], w[0][r*3+2], a0);
            a1 = fmaf(p0[r], w[1][r*3+0], a1);
            a1 = fmaf(p1[r], w[1][r*3+1], a1);
            a1 = fmaf(p2[r], w[1][r*3+2], a1);
            a2 = fmaf(p0[r], w[2][r*3+0], a2);
            a2 = fmaf(p1[r], w[2][r*3+1], a2);
            a2 = fmaf(p2[r], w[2][r*3+2], a2);

            d0  = fmaf(p1[r], w[0][r*3+0], d0);
            d0  = fmaf(p2[r], w[0][r*3+1], d0);
            d0  = fmaf(p3[r], w[0][r*3+2], d0);
            d1v = fmaf(p1[r], w[1][r*3+0], d1v);
            d1v = fmaf(p2[r], w[1][r*3+1], d1v);
            d1v = fmaf(p3[r], w[1][r*3+2], d1v);
            d2v = fmaf(p1[r], w[2][r*3+0], d2v);
            d2v = fmaf(p2[r], w[2][r*3+1], d2v);
            d2v = fmaf(p3[r], w[2][r*3+2], d2v);

            // output row y0+1 (uses window rows r+1)
            e0 = fmaf(p0[r+1], w[0][r*3+0], e0);
            e0 = fmaf(p1[r+1], w[0][r*3+1], e0);
            e0 = fmaf(p2[r+1], w[0][r*3+2], e0);
            e1 = fmaf(p0[r+1], w[1][r*3+0], e1);
            e1 = fmaf(p1[r+1], w[1][r*3+1], e1);
            e1 = fmaf(p2[r+1], w[1][r*3+2], e1);
            e2 = fmaf(p0[r+1], w[2][r*3+0], e2);
            e2 = fmaf(p1[r+1], w[2][r*3+1], e2);
            e2 = fmaf(p2[r+1], w[2][r*3+2], e2);

            f0 = fmaf(p1[r+1], w[0][r*3+0], f0);
            f0 = fmaf(p2[r+1], w[0][r*3+1], f0);
            f0 = fmaf(p3[r+1], w[0][r*3+2], f0);
            f1 = fmaf(p1[r+1], w[1][r*3+0], f1);
            f1 = fmaf(p2[r+1], w[1][r*3+1], f1);
            f1 = fmaf(p3[r+1], w[1][r*3+2], f1);
            f2 = fmaf(p1[r+1], w[2][r*3+0], f2);
            f2 = fmaf(p2[r+1], w[2][r*3+1], f2);
            f2 = fmaf(p3[r+1], w[2][r*3+2], f2);
        }

        size_t o = (size_t)x * 768;
        Pb0[o       ] = __float2half(a0);
        Pb0[o +  256] = __float2half(a1);
        Pb0[o +  512] = __float2half(a2);
        Pb0[o +  768] = __float2half(d0);
        Pb0[o + 1024] = __float2half(d1v);
        Pb0[o + 1280] = __float2half(d2v);

        Pb1[o       ] = __float2half(e0);
        Pb1[o +  256] = __float2half(e1);
        Pb1[o +  512] = __float2half(e2);
        Pb1[o +  768] = __float2half(f0);
        Pb1[o + 1024] = __float2half(f1);
        Pb1[o + 1280] = __float2half(f2);

        #pragma unroll
        for (int r = 0; r < 4; r++) {
            p0[r] = p2[r];
            p1[r] = p3[r];
            p2[r] = p4[r];
        }
    }
}

// =========== fp16 tensor-core GEMM: C[M,N] = A[M,K] @ B[N,K]^T ===============
// Block 128x128, warp tile 64x32, 2 CTAs/SM. Register double-buffered frags.
// (R15 configuration — no PDL.)
// EPI: 1 = gelu(+bias) -> fp16 Ch ; 2 = +bias+add -> fp16 Ch ONLY ;
//      3 = +bias -> fp16 Ch only
#define BK 64
#define RSTR 72
#define OPB (128 * RSTR * 2)
#define STG (2 * OPB)
#define NSTAGE 3

template<int EPI>
__global__ void __launch_bounds__(256, 2)
hgemm_kernel(const __half* __restrict__ A, const __half* __restrict__ Bw,
             const float* __restrict__ bias, const float* __restrict__ add,
             __half* __restrict__ Ch,
             int M, int N, int K, int nbn)
{
    extern __shared__ char dsm_raw[];
    uint32_t dbase = smem_u32(dsm_raw);

    int tid  = threadIdx.x;
    int lane = tid & 31;
    int wid  = tid >> 5;
    int wm   = wid >> 2;
    int wn   = wid & 3;

    int bid = blockIdx.x;
    int bm = bid / nbn;
    int bn = bid - bm * nbn;

    const __half* Ag = A  + (size_t)bm * 128 * K;
    const __half* Bg = Bw + (size_t)bn * 128 * K;

    auto load_stage = [&](int kt, int buf) {
        uint32_t sA = dbase + (uint32_t)buf * STG;
        uint32_t sB = sA + OPB;
        int kofs = kt * BK;
        #pragma unroll
        for (int i = 0; i < 4; i++) {
            int ci  = tid + 256 * i;
            int row = ci >> 3;
            int kc  = (ci & 7) * 8;
            const __half* ga = Ag + (size_t)row * K + kofs + kc;
            const __half* gb = Bg + (size_t)row * K + kofs + kc;
            uint32_t so = (uint32_t)(row * (RSTR * 2) + kc * 2);
            CP_ASYNC16(sA + so, ga);
            CP_ASYNC16(sB + so, gb);
        }
        CP_COMMIT();
    };

    float acc[4][4][4];
    #pragma unroll
    for (int i = 0; i < 4; i++)
        #pragma unroll
        for (int j = 0; j < 4; j++)
            #pragma unroll
            for (int r = 0; r < 4; r++) acc[i][j][r] = 0.f;

    int a_m  = (lane & 7) + ((lane >> 3) & 1) * 8;
    int a_kh = ((lane >> 4) & 1) * 8;
    int b_n  = (lane & 7) + ((lane >> 4) & 1) * 8;
    int b_kh = ((lane >> 3) & 1) * 8;

    uint32_t af[2][4][4];
    uint32_t bf[2][4][2];

    int NT = K / BK;
    load_stage(0, 0);
    load_stage(1, 1);

    for (int kt = 0; kt < NT; kt++) {
        if (kt + 2 < NT) {
            asm volatile("cp.async.wait_group 1;" ::: "memory");
        } else {
            asm volatile("cp.async.wait_group 0;" ::: "memory");
        }
        __syncthreads();
        if (kt + 2 < NT) load_stage(kt + 2, (kt + 2) % NSTAGE);

        uint32_t sA = dbase + (uint32_t)(kt % NSTAGE) * STG;
        uint32_t sB = sA + OPB;

        #pragma unroll
        for (int i = 0; i < 4; i++) {
            int m = wm * 64 + i * 16 + a_m;
            ldmatrix_x4(af[0][i][0], af[0][i][1], af[0][i][2], af[0][i][3],
                        sA + (uint32_t)((m * RSTR + a_kh) * 2));
        }
        #pragma unroll
        for (int j = 0; j < 2; j++) {
            int n = wn * 32 + j * 16 + b_n;
            ldmatrix_x4(bf[0][2*j][0], bf[0][2*j][1], bf[0][2*j+1][0], bf[0][2*j+1][1],
                        sB + (uint32_t)((n * RSTR + b_kh) * 2));
        }

        #pragma unroll
        for (int s = 0; s < 4; s++) {
            int cur = s & 1;
            if (s < 3) {
                int nxt = (s + 1) & 1;
                int k0 = (s + 1) * 16;
                #pragma unroll
                for (int i = 0; i < 4; i++) {
                    int m = wm * 64 + i * 16 + a_m;
                    ldmatrix_x4(af[nxt][i][0], af[nxt][i][1], af[nxt][i][2], af[nxt][i][3],
                                sA + (uint32_t)((m * RSTR + k0 + a_kh) * 2));
                }
                #pragma unroll
                for (int j = 0; j < 2; j++) {
                    int n = wn * 32 + j * 16 + b_n;
                    ldmatrix_x4(bf[nxt][2*j][0], bf[nxt][2*j][1],
                                bf[nxt][2*j+1][0], bf[nxt][2*j+1][1],
                                sB + (uint32_t)((n * RSTR + k0 + b_kh) * 2));
                }
            }
            #pragma unroll
            for (int i = 0; i < 4; i++)
                #pragma unroll
                for (int j = 0; j < 4; j++)
                    mma_f16(acc[i][j][0], acc[i][j][1], acc[i][j][2], acc[i][j][3],
                            af[cur][i][0], af[cur][i][1], af[cur][i][2], af[cur][i][3],
                            bf[cur][j][0], bf[cur][j][1]);
        }
    }

    int gid = lane >> 2;
    int tig = lane & 3;

    #pragma unroll
    for (int i = 0; i < 4; i++) {
        #pragma unroll
        for (int j = 0; j < 4; j++) {
            int rrow = bm*128 + wm*64 + i*16 + gid;
            int ncol = bn*128 + wn*32 + j*8 + tig*2;
            float b0v = bias[ncol], b1v = bias[ncol+1];

            float v0 = acc[i][j][0] + b0v;
            float v1 = acc[i][j][1] + b1v;
            float v2 = acc[i][j][2] + b0v;
            float v3 = acc[i][j][3] + b1v;
            if (EPI == 1) {
                v0 = gelu_exact(v0); v1 = gelu_exact(v1);
                v2 = gelu_exact(v2); v3 = gelu_exact(v3);
            }
            size_t o0 = (size_t)rrow * N + ncol;
            size_t o1 = (size_t)(rrow + 8) * N + ncol;
            if (EPI == 2) {
                float2 r0a = *(const float2*)(add + o0);
                float2 r1a = *(const float2*)(add + o1);
                v0 += r0a.x; v1 += r0a.y; v2 += r1a.x; v3 += r1a.y;
            }
            *(__half2*)(Ch + o0) = __floats2half2_rn(v0, v1);
            *(__half2*)(Ch + o1) = __floats2half2_rn(v2, v3);
        }
    }
}

// ==== 3x3 local attention: warp per PIXEL-PAIR, 16B loads, WRITE-ONLY out ===
__global__ void attn_kernel(const __half* __restrict__ qkv,
                            const __half* __restrict__ hnew,
                            float* __restrict__ out)
{
    int gtid = blockIdx.x * blockDim.x + threadIdx.x;
    int pair = gtid >> 5;
    int lane = gtid & 31;
    if (pair >= NPIX / 2) return;

    int pix0 = pair * 2;
    int x0 = pix0 & (Ww - 1);            // even
    int y  = (pix0 >> 6) & (Hh - 1);
    int b  = pix0 >> 12;

    int ch = lane * 8;                   // first owned channel

    uint4 q0u = *(const uint4*)(qkv + (size_t)pix0 * 768 + ch);
    uint4 q1u = *(const uint4*)(qkv + (size_t)(pix0 + 1) * 768 + ch);
    float2 q0[4], q1[4];
    q0[0] = u2f2(q0u.x); q0[1] = u2f2(q0u.y); q0[2] = u2f2(q0u.z); q0[3] = u2f2(q0u.w);
    q1[0] = u2f2(q1u.x); q1[1] = u2f2(q1u.y); q1[2] = u2f2(q1u.z); q1[3] = u2f2(q1u.w);

    const float scale = 0.0625f;   // 1/sqrt(256)
    float s0[9], s1[9];

    #pragma unroll
    for (int r = 0; r < 3; r++) {
        int ny = y + r - 1;
        bool rowok = (ny >= 0 && ny < Hh);
        #pragma unroll
        for (int c = 0; c < 4; c++) {
            int cx = x0 - 1 + c;
            bool ok = rowok && (cx >= 0 && cx < Ww);
            float p0 = 0.f, p1 = 0.f;
            if (ok) {
                uint4 ku = *(const uint4*)(qkv +
                    (size_t)((b*Hh + ny)*Ww + cx) * 768 + 256 + ch);
                float2 kf[4];
                kf[0] = u2f2(ku.x); kf[1] = u2f2(ku.y);
                kf[2] = u2f2(ku.z); kf[3] = u2f2(ku.w);
                #pragma unroll
                for (int rr = 0; rr < 4; rr++) {
                    if (c < 3) {
                        p0 = fmaf(q0[rr].x, kf[rr].x, p0);
                        p0 = fmaf(q0[rr].y, kf[rr].y, p0);
                    }
                    if (c > 0) {
                        p1 = fmaf(q1[rr].x, kf[rr].x, p1);
                        p1 = fmaf(q1[rr].y, kf[rr].y, p1);
                    }
                }
            }
            if (c < 3) {
                #pragma unroll
                for (int o = 16; o > 0; o >>= 1) p0 += __shfl_xor_sync(0xffffffff, p0, o);
                s0[r*3 + c] = ok ? p0 * scale : 0.f;
            }
            if (c > 0) {
                #pragma unroll
                for (int o = 16; o > 0; o >>= 1) p1 += __shfl_xor_sync(0xffffffff, p1, o);
                s1[r*3 + c - 1] = ok ? p1 * scale : 0.f;
            }
        }
    }

    float m0 = s0[0], m1 = s1[0];
    #pragma unroll
    for (int i = 1; i < 9; i++) { m0 = fmaxf(m0, s0[i]); m1 = fmaxf(m1, s1[i]); }
    float e0[9], e1[9], sum0 = 0.f, sum1 = 0.f;
    #pragma unroll
    for (int i = 0; i < 9; i++) {
        e0[i] = expf(s0[i] - m0); sum0 += e0[i];
        e1[i] = expf(s1[i] - m1); sum1 += e1[i];
    }
    float inv0 = 1.f / sum0, inv1 = 1.f / sum1;

    float2 a0[4], a1[4];
    #pragma unroll
    for (int r = 0; r < 4; r++) { a0[r] = make_float2(0.f,0.f); a1[r] = make_float2(0.f,0.f); }

    #pragma unroll
    for (int r = 0; r < 3; r++) {
        int ny = y + r - 1;
        bool rowok = (ny >= 0 && ny < Hh);
        #pragma unroll
        for (int c = 0; c < 4; c++) {
            int cx = x0 - 1 + c;
            bool ok = rowok && (cx >= 0 && cx < Ww);
            if (!ok) continue;
            float w0 = (c < 3) ? e0[r*3 + c] * inv0 : 0.f;
            float w1 = (c > 0) ? e1[r*3 + c - 1] * inv1 : 0.f;
            uint4 vu = *(const uint4*)(qkv +
                (size_t)((b*Hh + ny)*Ww + cx) * 768 + 512 + ch);
            float2 vf[4];
            vf[0] = u2f2(vu.x); vf[1] = u2f2(vu.y);
            vf[2] = u2f2(vu.z); vf[3] = u2f2(vu.w);
            #pragma unroll
            for (int rr = 0; rr < 4; rr++) {
                if (c < 3) {
                    a0[rr].x = fmaf(w0, vf[rr].x, a0[rr].x);
                    a0[rr].y = fmaf(w0, vf[rr].y, a0[rr].y);
                }
                if (c > 0) {
                    a1[rr].x = fmaf(w1, vf[rr].x, a1[rr].x);
                    a1[rr].y = fmaf(w1, vf[rr].y, a1[rr].y);
                }
            }
        }
    }

    // out = float(hnew fp16) + attn   (pure store, no RMW)
    {
        uint4 hu = *(const uint4*)(hnew + (size_t)pix0 * 256 + ch);
        float2 hf[4];
        hf[0] = u2f2(hu.x); hf[1] = u2f2(hu.y); hf[2] = u2f2(hu.z); hf[3] = u2f2(hu.w);
        float* ob = out + (size_t)pix0 * 256 + ch;
        *(float4*)(ob)     = make_float4(hf[0].x + a0[0].x, hf[0].y + a0[0].y,
                                         hf[1].x + a0[1].x, hf[1].y + a0[1].y);
        *(float4*)(ob + 4) = make_float4(hf[2].x + a0[2].x, hf[2].y + a0[2].y,
                                         hf[3].x + a0[3].x, hf[3].y + a0[3].y);
    }
    {
        uint4 hu = *(const uint4*)(hnew + (size_t)(pix0 + 1) * 256 + ch);
        float2 hf[4];
        hf[0] = u2f2(hu.x); hf[1] = u2f2(hu.y); hf[2] = u2f2(hu.z); hf[3] = u2f2(hu.w);
        float* ob = out + (size_t)(pix0 + 1) * 256 + ch;
        *(float4*)(ob)     = make_float4(hf[0].x + a1[0].x, hf[0].y + a1[0].y,
                                         hf[1].x + a1[1].x, hf[1].y + a1[1].y);
        *(float4*)(ob + 4) = make_float4(hf[2].x + a1[2].x, hf[2].y + a1[2].y,
                                         hf[3].x + a1[3].x, hf[3].y + a1[3].y);
    }
}

// ---------------- launch ------------------------------------------------------
extern "C" void kernel_launch(void* const* d_in, const int* in_sizes, int n_in,
                              void* d_out, int out_size)
{
    const float* h      = (const float*)d_in[0];
    const float* w_perc = (const float*)d_in[1];
    const float* b_perc = (const float*)d_in[2];
    const float* w_up1  = (const float*)d_in[3];
    const float* b_up1  = (const float*)d_in[4];
    const float* w_up2  = (const float*)d_in[5];
    const float* b_up2  = (const float*)d_in[6];
    const float* w_qkv  = (const float*)d_in[7];
    const float* b_qkv  = (const float*)d_in[8];
    float* out = (float*)d_out;

    __half *Ph, *HIDh, *HNEWh, *QKVh, *W1h, *W2h, *WQh;
    cudaGetSymbolAddress((void**)&Ph,    g_Ph);
    cudaGetSymbolAddress((void**)&HIDh,  g_HIDh);
    cudaGetSymbolAddress((void**)&HNEWh, g_HNEWh);
    cudaGetSymbolAddress((void**)&QKVh,  g_QKVh);
    cudaGetSymbolAddress((void**)&W1h,   g_W1h);
    cudaGetSymbolAddress((void**)&W2h,   g_W2h);
    cudaGetSymbolAddress((void**)&WQh,   g_WQh);

    size_t dsm = (size_t)NSTAGE * STG;   // 110592
    cudaFuncSetAttribute(hgemm_kernel<1>, cudaFuncAttributeMaxDynamicSharedMemorySize, (int)dsm);
    cudaFuncSetAttribute(hgemm_kernel<2>, cudaFuncAttributeMaxDynamicSharedMemorySize, (int)dsm);
    cudaFuncSetAttribute(hgemm_kernel<3>, cudaFuncAttributeMaxDynamicSharedMemorySize, (int)dsm);

    // 1) fused: dwconv (2 rows/block) + weight conversion, one launch
    dwconv_cvt_kernel<<<NCONVBLK + NCVTBLK, 256>>>(h, w_perc, b_perc, Ph,
                                                   w_up1, w_up2, w_qkv,
                                                   W1h, W2h, WQh);

    // 2) HIDh = gelu(Ph @ W1h^T + b_up1)  fp16 [NPIX, 512]
    {
        int nbm = NPIX / 128, nbn = 512 / 128;
        hgemm_kernel<1><<<nbm * nbn, 256, dsm>>>(Ph, W1h, b_up1, nullptr, HIDh,
                                                 NPIX, 512, 768, nbn);
    }
    // 3) h_new = HIDh @ W2h^T + b_up2 + h  -> HNEWh fp16 ONLY
    {
        int nbm = NPIX / 128, nbn = 256 / 128;
        hgemm_kernel<2><<<nbm * nbn, 256, dsm>>>(HIDh, W2h, b_up2, h, HNEWh,
                                                 NPIX, 256, 512, nbn);
    }
    // 4) QKVh = HNEWh @ WQh^T + b_qkv  fp16 [NPIX, 768]
    {
        int nbm = NPIX / 128, nbn = 768 / 128;
        hgemm_kernel<3><<<nbm * nbn, 256, dsm>>>(HNEWh, WQh, b_qkv, nullptr, QKVh,
                                                 NPIX, 768, 256, nbn);
    }
    // 5) out = float(HNEWh) + local_attn(QKVh)
    {
        int threads = 256;
        int blocks = (NPIX / 2 * 32) / threads;   // 4096
        attn_kernel<<<blocks, threads>>>(QKVh, HNEWh, out);
    }
}